// round 15
// baseline (speedup 1.0000x reference)
#include <cuda_runtime.h>
#include <cuda_fp16.h>
#include <math.h>
#include <stdint.h>

// ---------------------------------------------------------------------------
// DeepSeek V3 MLA attention block, S=1024, H=128.
// GEMMs + attention on fp16 mma.sync (fp32 accum). 3-stage cp.async GEMM.
// Attention: 128-row q-tile, 32 q-rows/warp, heavy-first CTA order,
// exp2-based softmax (log2e folded into q scale).
// ---------------------------------------------------------------------------

#define SEQ   1024
#define HID   7168
#define NH    128
#define DQ    192
#define DNOPE 128
#define DROPE 64
#define DVDIM 128

// fp32 scratch: merged q_a|kv_a output [1024, 2112] (qa | c_kv | k_pe)
__device__ __align__(256) float g_qkva[SEQ * 2112];
// fp16 operands
__device__ __align__(256) __half g_x16   [SEQ * HID];
__device__ __align__(256) __half g_qa16  [SEQ * 1536];
__device__ __align__(256) __half g_kva16 [SEQ * 512];
__device__ __align__(256) __half g_q16   [SEQ * (NH * DQ)];   // scaled*log2e, rope'd
__device__ __align__(256) __half g_kv16  [SEQ * (NH * 256)];
__device__ __align__(256) __half g_kpe16 [SEQ * DROPE];
__device__ __align__(256) __half g_ao16  [SEQ * (NH * DVDIM)];
__device__ __align__(256) __half g_wab16 [HID * 2112];        // wqa | wkva merged
__device__ __align__(256) __half g_wqb16 [1536 * 24576];
__device__ __align__(256) __half g_wkvb16[512 * 32768];
__device__ __align__(256) __half g_wo16  [16384 * HID];
// RoPE tables
__device__ float g_cosT[SEQ * 32];
__device__ float g_sinT[SEQ * 32];

// ---------------------------------------------------------------------------
// fp32 -> fp16 wide conversion: 16 floats per thread-iter (n % 16 == 0)
// ---------------------------------------------------------------------------
__global__ void cvt_f16_copy(const float* __restrict__ in, __half* __restrict__ out,
                             long long n16)
{
    long long stride = (long long)gridDim.x * blockDim.x;
    for (long long i = blockIdx.x * (long long)blockDim.x + threadIdx.x; i < n16; i += stride) {
        float4 v0 = ((const float4*)in)[i * 4 + 0];
        float4 v1 = ((const float4*)in)[i * 4 + 1];
        float4 v2 = ((const float4*)in)[i * 4 + 2];
        float4 v3 = ((const float4*)in)[i * 4 + 3];
        __half2 h[8];
        h[0] = __floats2half2_rn(v0.x, v0.y); h[1] = __floats2half2_rn(v0.z, v0.w);
        h[2] = __floats2half2_rn(v1.x, v1.y); h[3] = __floats2half2_rn(v1.z, v1.w);
        h[4] = __floats2half2_rn(v2.x, v2.y); h[5] = __floats2half2_rn(v2.z, v2.w);
        h[6] = __floats2half2_rn(v3.x, v3.y); h[7] = __floats2half2_rn(v3.z, v3.w);
        ((uint4*)out)[i * 2 + 0] = ((const uint4*)h)[0];
        ((uint4*)out)[i * 2 + 1] = ((const uint4*)h)[1];
    }
}

// Strided conversion (merged first-projection weight).
__global__ void cvt_f16_strided(const float* __restrict__ in, __half* __restrict__ out,
                                int rows, int cols8, int out_stride, int out_off)
{
    int total = rows * cols8;
    int stride = gridDim.x * blockDim.x;
    for (int i = blockIdx.x * blockDim.x + threadIdx.x; i < total; i += stride) {
        int r = i / cols8, c = i % cols8;
        float4 v0 = ((const float4*)in)[(size_t)i * 2 + 0];
        float4 v1 = ((const float4*)in)[(size_t)i * 2 + 1];
        __half2 h[4];
        h[0] = __floats2half2_rn(v0.x, v0.y); h[1] = __floats2half2_rn(v0.z, v0.w);
        h[2] = __floats2half2_rn(v1.x, v1.y); h[3] = __floats2half2_rn(v1.z, v1.w);
        *(uint4*)(out + (size_t)r * out_stride + out_off + c * 8) = *(const uint4*)h;
    }
}

__global__ void rope_table_kernel()
{
    int idx = blockIdx.x * blockDim.x + threadIdx.x;
    if (idx >= SEQ * 32) return;
    int row = idx >> 5, j = idx & 31;
    double ang = (double)row * pow(10000.0, -(double)j / 32.0);
    double sd, cd;
    sincos(ang, &sd, &cd);
    g_cosT[idx] = (float)cd;
    g_sinT[idx] = (float)sd;
}

// ---------------------------------------------------------------------------
__device__ __forceinline__ void cp_async16(void* dst, const void* src, bool pred) {
    uint32_t d = (uint32_t)__cvta_generic_to_shared(dst);
    int sz = pred ? 16 : 0;
    asm volatile("cp.async.cg.shared.global [%0], [%1], 16, %2;\n"
                 :: "r"(d), "l"(src), "r"(sz));
}
__device__ __forceinline__ void cp_commit() {
    asm volatile("cp.async.commit_group;\n");
}
template <int N>
__device__ __forceinline__ void cp_wait() {
    asm volatile("cp.async.wait_group %0;\n" :: "n"(N));
}
__device__ __forceinline__ void ldmatrix_x4(uint32_t& r0, uint32_t& r1,
                                            uint32_t& r2, uint32_t& r3, uint32_t addr) {
    asm volatile("ldmatrix.sync.aligned.m8n8.x4.shared.b16 {%0,%1,%2,%3}, [%4];"
                 : "=r"(r0), "=r"(r1), "=r"(r2), "=r"(r3) : "r"(addr));
}
__device__ __forceinline__ void ldmatrix_x4_trans(uint32_t& r0, uint32_t& r1,
                                                  uint32_t& r2, uint32_t& r3, uint32_t addr) {
    asm volatile("ldmatrix.sync.aligned.m8n8.x4.trans.shared.b16 {%0,%1,%2,%3}, [%4];"
                 : "=r"(r0), "=r"(r1), "=r"(r2), "=r"(r3) : "r"(addr));
}
__device__ __forceinline__ void mma16816(float* c, const uint32_t* a, uint32_t b0, uint32_t b1) {
    asm volatile(
        "mma.sync.aligned.m16n8k16.row.col.f32.f16.f16.f32 "
        "{%0,%1,%2,%3}, {%4,%5,%6,%7}, {%8,%9}, {%0,%1,%2,%3};\n"
        : "+f"(c[0]), "+f"(c[1]), "+f"(c[2]), "+f"(c[3])
        : "r"(a[0]), "r"(a[1]), "r"(a[2]), "r"(a[3]), "r"(b0), "r"(b1));
}
__device__ __forceinline__ uint32_t pack_h2(float a, float b) {
    __half2 h = __floats2half2_rn(a, b);
    return *(uint32_t*)&h;
}

// ---------------------------------------------------------------------------
// fp16 GEMM, 3-stage cp.async pipeline (56.8KB smem -> 3 CTAs/SM).
// ---------------------------------------------------------------------------
#define AS_STRIDE 40
#define BS_STRIDE 136
#define AS_HALVES (128 * AS_STRIDE)          // 5120
#define BS_HALVES (32 * BS_STRIDE)           // 4352
#define NSTAGE 3
#define GEMM_SMEM_BYTES (NSTAGE * (AS_HALVES + BS_HALVES) * 2)   // 56832

template <bool HALF_OUT>
__global__ __launch_bounds__(128, 3)
void gemm_f16_t(const __half* __restrict__ A, const __half* __restrict__ B,
                void* __restrict__ Cv, float cscale, int N, int K,
                int lda, int ldb, int ldc)
{
    extern __shared__ __half smg[];
    __half* Asb = smg;
    __half* Bsb = smg + NSTAGE * AS_HALVES;

    const int tid  = threadIdx.x;
    const int warp = tid >> 5, lane = tid & 31;
    const int g    = lane >> 2, t4 = lane & 3;
    const int wm   = warp >> 1, wn = warp & 1;
    const int m0   = blockIdx.y * 128;
    const int n0   = blockIdx.x * 128;

    const int l16  = lane & 15;
    const int lhi8 = (lane >> 4) << 3;

    float acc[4][8][4];
    #pragma unroll
    for (int mt = 0; mt < 4; mt++)
        #pragma unroll
        for (int nt = 0; nt < 8; nt++)
            #pragma unroll
            for (int r = 0; r < 4; r++) acc[mt][nt][r] = 0.f;

    const int nk = K >> 5;
    const int ar = tid >> 2, aseg = (tid & 3) << 3;
    const int br = tid >> 4, bseg = (tid & 15) << 3;

    auto load_stage = [&](int t, int buf) {
        __half* As = Asb + buf * AS_HALVES;
        __half* Bs = Bsb + buf * BS_HALVES;
        int k0 = t << 5;
        #pragma unroll
        for (int i = 0; i < 4; i++) {
            int row = ar + 32 * i;
            cp_async16(&As[row * AS_STRIDE + aseg],
                       A + (size_t)(m0 + row) * lda + k0 + aseg, true);
        }
        #pragma unroll
        for (int i = 0; i < 4; i++) {
            int row = br + 8 * i;
            int col = n0 + bseg;
            bool p = col < N;
            const __half* src = p ? (B + (size_t)(k0 + row) * ldb + col) : B;
            cp_async16(&Bs[row * BS_STRIDE + bseg], src, p);
        }
        cp_commit();
    };

    load_stage(0, 0);
    load_stage(1, 1);

    int buf = 0, lbuf = 2;
    for (int t = 0; t < nk; t++) {
        cp_wait<1>();
        __syncthreads();
        if (t + 2 < nk) load_stage(t + 2, lbuf);
        else            cp_commit();

        uint32_t a_base = (uint32_t)__cvta_generic_to_shared(Asb + buf * AS_HALVES);
        uint32_t b_base = (uint32_t)__cvta_generic_to_shared(Bsb + buf * BS_HALVES);

        #pragma unroll
        for (int ks = 0; ks < 2; ks++) {
            int k16 = ks << 4;
            uint32_t af[4][4];
            #pragma unroll
            for (int mt = 0; mt < 4; mt++) {
                uint32_t addr = a_base +
                    ((wm * 64 + mt * 16 + l16) * AS_STRIDE + k16 + lhi8) * 2u;
                ldmatrix_x4(af[mt][0], af[mt][1], af[mt][2], af[mt][3], addr);
            }
            uint32_t bf[4][4];
            #pragma unroll
            for (int ntp = 0; ntp < 4; ntp++) {
                uint32_t addr = b_base +
                    ((k16 + l16) * BS_STRIDE + wn * 64 + ntp * 16 + lhi8) * 2u;
                ldmatrix_x4_trans(bf[ntp][0], bf[ntp][1], bf[ntp][2], bf[ntp][3], addr);
            }
            #pragma unroll
            for (int mt = 0; mt < 4; mt++)
                #pragma unroll
                for (int nt = 0; nt < 8; nt++)
                    mma16816(acc[mt][nt], af[mt],
                             bf[nt >> 1][(nt & 1) * 2 + 0], bf[nt >> 1][(nt & 1) * 2 + 1]);
        }
        buf  = (buf  == 2) ? 0 : buf  + 1;
        lbuf = (lbuf == 2) ? 0 : lbuf + 1;
    }

    #pragma unroll
    for (int mt = 0; mt < 4; mt++) {
        int row = m0 + wm * 64 + mt * 16 + g;
        #pragma unroll
        for (int nt = 0; nt < 8; nt++) {
            int col = n0 + wn * 64 + nt * 8 + t4 * 2;
            if (col < N) {
                float* c = acc[mt][nt];
                if (HALF_OUT) {
                    __half* C = (__half*)Cv;
                    *(__half2*)(C + (size_t)row * ldc + col) =
                        __floats2half2_rn(c[0] * cscale, c[1] * cscale);
                    *(__half2*)(C + (size_t)(row + 8) * ldc + col) =
                        __floats2half2_rn(c[2] * cscale, c[3] * cscale);
                } else {
                    float* C = (float*)Cv;
                    *(float2*)(C + (size_t)row * ldc + col)       = make_float2(c[0], c[1]);
                    *(float2*)(C + (size_t)(row + 8) * ldc + col) = make_float2(c[2], c[3]);
                }
            }
        }
    }
}

// ---------------------------------------------------------------------------
// RMSNorm fp32 -> fp16
// ---------------------------------------------------------------------------
__global__ void rmsnorm_f16(const float* __restrict__ x, const float* __restrict__ w,
                            __half* __restrict__ out, int cols, int in_stride, int out_stride)
{
    const float* p = x + (size_t)blockIdx.x * in_stride;
    __half* q = out + (size_t)blockIdx.x * out_stride;
    float s = 0.f;
    for (int c = threadIdx.x; c < cols; c += blockDim.x) { float v = p[c]; s += v * v; }
    __shared__ float red[256];
    red[threadIdx.x] = s;
    __syncthreads();
    for (int o = 128; o > 0; o >>= 1) {
        if (threadIdx.x < o) red[threadIdx.x] += red[threadIdx.x + o];
        __syncthreads();
    }
    float scale = rsqrtf(red[0] / (float)cols + 1e-6f);
    for (int c = threadIdx.x; c < cols; c += blockDim.x)
        q[c] = __float2half_rn(p[c] * scale * w[c]);
}

// ---------------------------------------------------------------------------
// RoPE
// ---------------------------------------------------------------------------
__global__ void rope_kpe16_kernel(const float* __restrict__ qkva, __half* __restrict__ kpe)
{
    int idx = blockIdx.x * blockDim.x + threadIdx.x;
    if (idx >= SEQ * 32) return;
    int row = idx >> 5, j = idx & 31;
    float c = g_cosT[idx], s = g_sinT[idx];
    const float* p = qkva + (size_t)row * 2112 + 2048;
    float a = p[j], b = p[j + 32];
    kpe[row * 64 + j]      = __float2half_rn(a * c - b * s);
    kpe[row * 64 + j + 32] = __float2half_rn(b * c + a * s);
}

__global__ void rope_q16_kernel(__half* __restrict__ q)
{
    int idx = blockIdx.x * blockDim.x + threadIdx.x;
    if (idx >= SEQ * NH * 32) return;
    int row = idx >> 12;
    int rem = idx & 4095;
    int h   = rem >> 5, j = rem & 31;
    float c = g_cosT[row * 32 + j], s = g_sinT[row * 32 + j];
    __half* p = q + (size_t)row * (NH * DQ) + h * DQ + DNOPE;
    float a = __half2float(p[j]), b = __half2float(p[j + 32]);
    p[j]      = __float2half_rn(a * c - b * s);
    p[j + 32] = __float2half_rn(b * c + a * s);
}

// ---------------------------------------------------------------------------
// Tensor-core flash attention: 128-row q-tile, 4 warps, 32 q-rows/warp.
// Heavy-first CTA order; exp2 softmax (q pre-scaled by 192^-0.5 * log2e).
// grid = (8 mblk, 128 heads), 128 threads.
// ---------------------------------------------------------------------------
#define AQ_STR 200
#define AK_STR 200
#define AV_STR 136
#define AT_QS  0
#define AT_KS  (128 * AQ_STR)                  // 25600
#define AT_VS  (AT_KS + 64 * AK_STR)           // 38400
#define AT_SMEM_HALVES (AT_VS + 64 * AV_STR)   // 47104 halves = 94208 B

__global__ __launch_bounds__(128)
void attn_mma(const __half* __restrict__ Q, const __half* __restrict__ KV,
              const __half* __restrict__ KPE, __half* __restrict__ O)
{
    extern __shared__ __half sh[];
    __half* Qs = sh + AT_QS;
    __half* Ks = sh + AT_KS;
    __half* Vs = sh + AT_VS;

    const int h    = blockIdx.y;
    const int mblk = gridDim.x - 1 - blockIdx.x;   // heavy CTAs scheduled first
    const int m0   = mblk * 128;
    const int tid  = threadIdx.x;
    const int warp = tid >> 5, lane = tid & 31;
    const int g    = lane >> 2, t4 = lane & 3;
    const int l16  = lane & 15;
    const int lhi8 = (lane >> 4) << 3;

    // Q: 128 rows x 24 x 16B chunks (q16 pre-scaled by 192^-0.5 * log2e)
    for (int c = tid; c < 128 * 24; c += 128) {
        int qr = c / 24, sg = c % 24;
        cp_async16(&Qs[qr * AQ_STR + sg * 8],
                   Q + (size_t)(m0 + qr) * (NH * DQ) + h * DQ + sg * 8, true);
    }
    cp_commit();

    float accO[2][16][4];
    #pragma unroll
    for (int mt = 0; mt < 2; mt++)
        #pragma unroll
        for (int i = 0; i < 16; i++)
            #pragma unroll
            for (int r = 0; r < 4; r++) accO[mt][i][r] = 0.f;
    float m_run[2][2] = {{-1e30f, -1e30f}, {-1e30f, -1e30f}};
    float l_run[2][2] = {{0.f, 0.f}, {0.f, 0.f}};

    uint32_t qbase = (uint32_t)__cvta_generic_to_shared(Qs);
    uint32_t kbase = (uint32_t)__cvta_generic_to_shared(Ks);
    uint32_t vbase = (uint32_t)__cvta_generic_to_shared(Vs);

    const int ntiles = 2 * mblk + 2;            // causal: k-tiles 0 .. 2*mblk+1
    for (int nt = 0; nt < ntiles; nt++) {
        int n0 = nt * 64;
        for (int c = tid; c < 64 * 24; c += 128) {
            int kr = c / 24, sg = c % 24;
            if (sg < 16)
                cp_async16(&Ks[kr * AK_STR + sg * 8],
                           KV + (size_t)(n0 + kr) * (NH * 256) + h * 256 + sg * 8, true);
            else
                cp_async16(&Ks[kr * AK_STR + 128 + (sg - 16) * 8],
                           KPE + (size_t)(n0 + kr) * 64 + (sg - 16) * 8, true);
        }
        for (int c = tid; c < 64 * 16; c += 128) {
            int vr = c / 16, sg = c % 16;
            cp_async16(&Vs[vr * AV_STR + sg * 8],
                       KV + (size_t)(n0 + vr) * (NH * 256) + h * 256 + 128 + sg * 8, true);
        }
        cp_commit();
        cp_wait<0>();
        __syncthreads();

        float sacc[2][8][4];
        #pragma unroll
        for (int mt = 0; mt < 2; mt++)
            #pragma unroll
            for (int nb = 0; nb < 8; nb++)
                #pragma unroll
                for (int r = 0; r < 4; r++) sacc[mt][nb][r] = 0.f;

        // S = Q K^T : K fragments shared across the 2 m-blocks
        #pragma unroll
        for (int kk = 0; kk < 12; kk++) {
            uint32_t aq[2][4];
            #pragma unroll
            for (int mt = 0; mt < 2; mt++)
                ldmatrix_x4(aq[mt][0], aq[mt][1], aq[mt][2], aq[mt][3],
                            qbase + ((warp * 32 + mt * 16 + l16) * AQ_STR + kk * 16 + lhi8) * 2u);
            #pragma unroll
            for (int nb2 = 0; nb2 < 4; nb2++) {
                uint32_t bk[4];
                ldmatrix_x4(bk[0], bk[1], bk[2], bk[3],
                            kbase + ((nb2 * 16 + l16) * AK_STR + kk * 16 + lhi8) * 2u);
                #pragma unroll
                for (int mt = 0; mt < 2; mt++) {
                    mma16816(sacc[mt][nb2 * 2],     aq[mt], bk[0], bk[2]);
                    mma16816(sacc[mt][nb2 * 2 + 1], aq[mt], bk[1], bk[3]);
                }
            }
        }

        // causal mask only on diagonal-crossing tiles (nt >= 2*mblk)
        if (nt >= 2 * mblk) {
            #pragma unroll
            for (int mt = 0; mt < 2; mt++) {
                int row0 = m0 + warp * 32 + mt * 16 + g;
                #pragma unroll
                for (int nb = 0; nb < 8; nb++) {
                    int c0 = n0 + nb * 8 + 2 * t4;
                    if (c0     > row0)     sacc[mt][nb][0] = -1e30f;
                    if (c0 + 1 > row0)     sacc[mt][nb][1] = -1e30f;
                    if (c0     > row0 + 8) sacc[mt][nb][2] = -1e30f;
                    if (c0 + 1 > row0 + 8) sacc[mt][nb][3] = -1e30f;
                }
            }
        }

        #pragma unroll
        for (int mt = 0; mt < 2; mt++) {
            float mx0 = -1e30f, mx1 = -1e30f;
            #pragma unroll
            for (int nb = 0; nb < 8; nb++) {
                mx0 = fmaxf(mx0, fmaxf(sacc[mt][nb][0], sacc[mt][nb][1]));
                mx1 = fmaxf(mx1, fmaxf(sacc[mt][nb][2], sacc[mt][nb][3]));
            }
            mx0 = fmaxf(mx0, __shfl_xor_sync(0xffffffffu, mx0, 1));
            mx0 = fmaxf(mx0, __shfl_xor_sync(0xffffffffu, mx0, 2));
            mx1 = fmaxf(mx1, __shfl_xor_sync(0xffffffffu, mx1, 1));
            mx1 = fmaxf(mx1, __shfl_xor_sync(0xffffffffu, mx1, 2));

            float mn0 = fmaxf(m_run[mt][0], mx0), mn1 = fmaxf(m_run[mt][1], mx1);
            float corr0 = exp2f(m_run[mt][0] - mn0), corr1 = exp2f(m_run[mt][1] - mn1);

            float ls0 = 0.f, ls1 = 0.f;
            #pragma unroll
            for (int nb = 0; nb < 8; nb++) {
                float p0 = exp2f(sacc[mt][nb][0] - mn0);
                float p1 = exp2f(sacc[mt][nb][1] - mn0);
                float p2 = exp2f(sacc[mt][nb][2] - mn1);
                float p3 = exp2f(sacc[mt][nb][3] - mn1);
                ls0 += p0 + p1;
                ls1 += p2 + p3;
                sacc[mt][nb][0] = p0; sacc[mt][nb][1] = p1;
                sacc[mt][nb][2] = p2; sacc[mt][nb][3] = p3;
            }
            ls0 += __shfl_xor_sync(0xffffffffu, ls0, 1);
            ls0 += __shfl_xor_sync(0xffffffffu, ls0, 2);
            ls1 += __shfl_xor_sync(0xffffffffu, ls1, 1);
            ls1 += __shfl_xor_sync(0xffffffffu, ls1, 2);
            l_run[mt][0] = l_run[mt][0] * corr0 + ls0;
            l_run[mt][1] = l_run[mt][1] * corr1 + ls1;
            m_run[mt][0] = mn0; m_run[mt][1] = mn1;

            #pragma unroll
            for (int i = 0; i < 16; i++) {
                accO[mt][i][0] *= corr0; accO[mt][i][1] *= corr0;
                accO[mt][i][2] *= corr1; accO[mt][i][3] *= corr1;
            }
        }

        // O += P @ V : V fragments shared across the 2 m-blocks
        #pragma unroll
        for (int kb = 0; kb < 4; kb++) {
            uint32_t pa[2][4];
            #pragma unroll
            for (int mt = 0; mt < 2; mt++) {
                pa[mt][0] = pack_h2(sacc[mt][2 * kb][0],     sacc[mt][2 * kb][1]);
                pa[mt][1] = pack_h2(sacc[mt][2 * kb][2],     sacc[mt][2 * kb][3]);
                pa[mt][2] = pack_h2(sacc[mt][2 * kb + 1][0], sacc[mt][2 * kb + 1][1]);
                pa[mt][3] = pack_h2(sacc[mt][2 * kb + 1][2], sacc[mt][2 * kb + 1][3]);
            }
            #pragma unroll
            for (int np = 0; np < 8; np++) {
                uint32_t bv[4];
                ldmatrix_x4_trans(bv[0], bv[1], bv[2], bv[3],
                                  vbase + ((kb * 16 + l16) * AV_STR + np * 16 + lhi8) * 2u);
                #pragma unroll
                for (int mt = 0; mt < 2; mt++) {
                    mma16816(accO[mt][np * 2],     pa[mt], bv[0], bv[1]);
                    mma16816(accO[mt][np * 2 + 1], pa[mt], bv[2], bv[3]);
                }
            }
        }
        __syncthreads();
    }

    #pragma unroll
    for (int mt = 0; mt < 2; mt++) {
        float inv0 = 1.f / l_run[mt][0], inv1 = 1.f / l_run[mt][1];
        int row0 = m0 + warp * 32 + mt * 16 + g;
        __half* O0 = O + (size_t)row0 * (NH * DVDIM) + h * DVDIM;
        __half* O1 = O0 + 8 * (size_t)(NH * DVDIM);
        #pragma unroll
        for (int np = 0; np < 16; np++) {
            int col = np * 8 + 2 * t4;
            *(__half2*)(O0 + col) =
                __floats2half2_rn(accO[mt][np][0] * inv0, accO[mt][np][1] * inv0);
            *(__half2*)(O1 + col) =
                __floats2half2_rn(accO[mt][np][2] * inv1, accO[mt][np][3] * inv1);
        }
    }
}

// ---------------------------------------------------------------------------
extern "C" void kernel_launch(void* const* d_in, const int* in_sizes, int n_in,
                              void* d_out, int out_size)
{
    const float* x    = (const float*)d_in[0];
    // d_in[1] = position_ids = arange(S); row index used directly (dtype-proof).
    const float* wqa  = (const float*)d_in[2];
    const float* qln  = (const float*)d_in[3];
    const float* wqb  = (const float*)d_in[4];
    const float* wkva = (const float*)d_in[5];
    const float* kvln = (const float*)d_in[6];
    const float* wkvb = (const float*)d_in[7];
    const float* wo   = (const float*)d_in[8];
    float*       out  = (float*)d_out;

    float *qkva;
    __half *x16, *qa16, *kva16, *q16, *kv16, *kpe16, *ao16;
    __half *wab16, *wqb16, *wkvb16, *wo16;
    cudaGetSymbolAddress((void**)&qkva,   g_qkva);
    cudaGetSymbolAddress((void**)&x16,    g_x16);
    cudaGetSymbolAddress((void**)&qa16,   g_qa16);
    cudaGetSymbolAddress((void**)&kva16,  g_kva16);
    cudaGetSymbolAddress((void**)&q16,    g_q16);
    cudaGetSymbolAddress((void**)&kv16,   g_kv16);
    cudaGetSymbolAddress((void**)&kpe16,  g_kpe16);
    cudaGetSymbolAddress((void**)&ao16,   g_ao16);
    cudaGetSymbolAddress((void**)&wab16,  g_wab16);
    cudaGetSymbolAddress((void**)&wqb16,  g_wqb16);
    cudaGetSymbolAddress((void**)&wkvb16, g_wkvb16);
    cudaGetSymbolAddress((void**)&wo16,   g_wo16);

    static cudaStream_t s1 = nullptr;
    static cudaEvent_t ev_root = nullptr, ev_q = nullptr, ev_k = nullptr, ev_o = nullptr;
    if (s1 == nullptr) {
        cudaStreamCreateWithFlags(&s1, cudaStreamNonBlocking);
        cudaEventCreateWithFlags(&ev_root, cudaEventDisableTiming);
        cudaEventCreateWithFlags(&ev_q,    cudaEventDisableTiming);
        cudaEventCreateWithFlags(&ev_k,    cudaEventDisableTiming);
        cudaEventCreateWithFlags(&ev_o,    cudaEventDisableTiming);
    }

    auto cvt_on = [&](cudaStream_t st, const float* src, __half* dst, long long n) {
        long long n16 = n / 16;
        int blocks = (int)((n16 + 255) / 256);
        if (blocks > 16384) blocks = 16384;
        cvt_f16_copy<<<blocks, 256, 0, st>>>(src, dst, n16);
    };

    // fork: side stream converts the three big weights
    cudaEventRecord(ev_root, 0);
    cudaStreamWaitEvent(s1, ev_root, 0);
    cvt_on(s1, wqb,  wqb16,  (long long)1536 * 24576);
    cudaEventRecord(ev_q, s1);
    cvt_on(s1, wkvb, wkvb16, (long long)512 * 32768);
    cudaEventRecord(ev_k, s1);
    cvt_on(s1, wo,   wo16,   (long long)16384 * HID);
    cudaEventRecord(ev_o, s1);

    // main stream
    cvt_on(0, x, x16, (long long)SEQ * HID);
    cvt_f16_strided<<<2048, 256>>>(wqa,  wab16, HID, 1536 / 8, 2112, 0);
    cvt_f16_strided<<<1024, 256>>>(wkva, wab16, HID, 576 / 8,  2112, 1536);
    rope_table_kernel<<<(SEQ * 32 + 255) / 256, 256>>>();

    // 192^-0.5 * log2(e): softmax computed base-2 (exp2f), fold the base change
    // into the linear q scaling (rope is linear, so it commutes).
    const float qscale = 0.07216878364870323f * 1.4426950408889634f;

    cudaFuncSetAttribute(gemm_f16_t<false>, cudaFuncAttributeMaxDynamicSharedMemorySize,
                         GEMM_SMEM_BYTES);
    cudaFuncSetAttribute(gemm_f16_t<true>, cudaFuncAttributeMaxDynamicSharedMemorySize,
                         GEMM_SMEM_BYTES);

    // 1: merged q_a|kv_a projection -> fp32 [1024, 2112]
    gemm_f16_t<false><<<dim3(17, 8), 128, GEMM_SMEM_BYTES>>>(
        x16, wab16, qkva, 1.f, 2112, HID, HID, 2112, 2112);

    // 2: rmsnorms -> fp16
    rmsnorm_f16<<<SEQ, 256>>>(qkva,        qln,  qa16,  1536, 2112, 1536);
    rmsnorm_f16<<<SEQ, 256>>>(qkva + 1536, kvln, kva16, 512,  2112, 512);

    // 3: rope on k_pe
    rope_kpe16_kernel<<<(SEQ * 32 + 255) / 256, 256>>>(qkva, kpe16);

    // 4: q projection (needs wqb16) + rope on q_pe
    cudaStreamWaitEvent(0, ev_q, 0);
    gemm_f16_t<true><<<dim3(24576 / 128, 8), 128, GEMM_SMEM_BYTES>>>(
        qa16, wqb16, q16, qscale, 24576, 1536, 1536, 24576, 24576);
    rope_q16_kernel<<<(SEQ * NH * 32 + 255) / 256, 256>>>(q16);

    // 5: kv projection (needs wkvb16)
    cudaStreamWaitEvent(0, ev_k, 0);
    gemm_f16_t<true><<<dim3(32768 / 128, 8), 128, GEMM_SMEM_BYTES>>>(
        kva16, wkvb16, kv16, 1.f, 32768, 512, 512, 32768, 32768);

    // 6: attention (128-row q-tiles, heavy-first order)
    cudaFuncSetAttribute(attn_mma, cudaFuncAttributeMaxDynamicSharedMemorySize,
                         AT_SMEM_HALVES * 2);
    attn_mma<<<dim3(8, NH), 128, AT_SMEM_HALVES * 2>>>(q16, kv16, kpe16, ao16);

    // 7: output projection (needs wo16) -> d_out
    cudaStreamWaitEvent(0, ev_o, 0);
    gemm_f16_t<false><<<dim3(HID / 128, 8), 128, GEMM_SMEM_BYTES>>>(
        ao16, wo16, out, 1.f, HID, NH * DVDIM, NH * DVDIM, HID, HID);
}

// round 16
// speedup vs baseline: 1.0525x; 1.0525x over previous
#include <cuda_runtime.h>
#include <cuda_fp16.h>
#include <math.h>
#include <stdint.h>

// ---------------------------------------------------------------------------
// DeepSeek V3 MLA attention block, S=1024, H=128.
// GEMMs: fp16 mma.sync, BM=64 x BN=128 tiles (wave-quantization fix),
// 3-stage cp.async. Attention: 128-row q-tile, 32 q-rows/warp, exp2 softmax.
// ---------------------------------------------------------------------------

#define SEQ   1024
#define HID   7168
#define NH    128
#define DQ    192
#define DNOPE 128
#define DROPE 64
#define DVDIM 128

// fp32 scratch: merged q_a|kv_a output [1024, 2112] (qa | c_kv | k_pe)
__device__ __align__(256) float g_qkva[SEQ * 2112];
// fp16 operands
__device__ __align__(256) __half g_x16   [SEQ * HID];
__device__ __align__(256) __half g_qa16  [SEQ * 1536];
__device__ __align__(256) __half g_kva16 [SEQ * 512];
__device__ __align__(256) __half g_q16   [SEQ * (NH * DQ)];   // scaled*log2e, rope'd
__device__ __align__(256) __half g_kv16  [SEQ * (NH * 256)];
__device__ __align__(256) __half g_kpe16 [SEQ * DROPE];
__device__ __align__(256) __half g_ao16  [SEQ * (NH * DVDIM)];
__device__ __align__(256) __half g_wab16 [HID * 2112];        // wqa | wkva merged
__device__ __align__(256) __half g_wqb16 [1536 * 24576];
__device__ __align__(256) __half g_wkvb16[512 * 32768];
__device__ __align__(256) __half g_wo16  [16384 * HID];
// RoPE tables
__device__ float g_cosT[SEQ * 32];
__device__ float g_sinT[SEQ * 32];

// ---------------------------------------------------------------------------
// fp32 -> fp16 wide conversion: 16 floats per thread-iter (n % 16 == 0)
// ---------------------------------------------------------------------------
__global__ void cvt_f16_copy(const float* __restrict__ in, __half* __restrict__ out,
                             long long n16)
{
    long long stride = (long long)gridDim.x * blockDim.x;
    for (long long i = blockIdx.x * (long long)blockDim.x + threadIdx.x; i < n16; i += stride) {
        float4 v0 = ((const float4*)in)[i * 4 + 0];
        float4 v1 = ((const float4*)in)[i * 4 + 1];
        float4 v2 = ((const float4*)in)[i * 4 + 2];
        float4 v3 = ((const float4*)in)[i * 4 + 3];
        __half2 h[8];
        h[0] = __floats2half2_rn(v0.x, v0.y); h[1] = __floats2half2_rn(v0.z, v0.w);
        h[2] = __floats2half2_rn(v1.x, v1.y); h[3] = __floats2half2_rn(v1.z, v1.w);
        h[4] = __floats2half2_rn(v2.x, v2.y); h[5] = __floats2half2_rn(v2.z, v2.w);
        h[6] = __floats2half2_rn(v3.x, v3.y); h[7] = __floats2half2_rn(v3.z, v3.w);
        ((uint4*)out)[i * 2 + 0] = ((const uint4*)h)[0];
        ((uint4*)out)[i * 2 + 1] = ((const uint4*)h)[1];
    }
}

// Strided conversion (merged first-projection weight).
__global__ void cvt_f16_strided(const float* __restrict__ in, __half* __restrict__ out,
                                int rows, int cols8, int out_stride, int out_off)
{
    int total = rows * cols8;
    int stride = gridDim.x * blockDim.x;
    for (int i = blockIdx.x * blockDim.x + threadIdx.x; i < total; i += stride) {
        int r = i / cols8, c = i % cols8;
        float4 v0 = ((const float4*)in)[(size_t)i * 2 + 0];
        float4 v1 = ((const float4*)in)[(size_t)i * 2 + 1];
        __half2 h[4];
        h[0] = __floats2half2_rn(v0.x, v0.y); h[1] = __floats2half2_rn(v0.z, v0.w);
        h[2] = __floats2half2_rn(v1.x, v1.y); h[3] = __floats2half2_rn(v1.z, v1.w);
        *(uint4*)(out + (size_t)r * out_stride + out_off + c * 8) = *(const uint4*)h;
    }
}

__global__ void rope_table_kernel()
{
    int idx = blockIdx.x * blockDim.x + threadIdx.x;
    if (idx >= SEQ * 32) return;
    int row = idx >> 5, j = idx & 31;
    double ang = (double)row * pow(10000.0, -(double)j / 32.0);
    double sd, cd;
    sincos(ang, &sd, &cd);
    g_cosT[idx] = (float)cd;
    g_sinT[idx] = (float)sd;
}

// ---------------------------------------------------------------------------
__device__ __forceinline__ void cp_async16(void* dst, const void* src, bool pred) {
    uint32_t d = (uint32_t)__cvta_generic_to_shared(dst);
    int sz = pred ? 16 : 0;
    asm volatile("cp.async.cg.shared.global [%0], [%1], 16, %2;\n"
                 :: "r"(d), "l"(src), "r"(sz));
}
__device__ __forceinline__ void cp_commit() {
    asm volatile("cp.async.commit_group;\n");
}
template <int N>
__device__ __forceinline__ void cp_wait() {
    asm volatile("cp.async.wait_group %0;\n" :: "n"(N));
}
__device__ __forceinline__ void ldmatrix_x4(uint32_t& r0, uint32_t& r1,
                                            uint32_t& r2, uint32_t& r3, uint32_t addr) {
    asm volatile("ldmatrix.sync.aligned.m8n8.x4.shared.b16 {%0,%1,%2,%3}, [%4];"
                 : "=r"(r0), "=r"(r1), "=r"(r2), "=r"(r3) : "r"(addr));
}
__device__ __forceinline__ void ldmatrix_x4_trans(uint32_t& r0, uint32_t& r1,
                                                  uint32_t& r2, uint32_t& r3, uint32_t addr) {
    asm volatile("ldmatrix.sync.aligned.m8n8.x4.trans.shared.b16 {%0,%1,%2,%3}, [%4];"
                 : "=r"(r0), "=r"(r1), "=r"(r2), "=r"(r3) : "r"(addr));
}
__device__ __forceinline__ void mma16816(float* c, const uint32_t* a, uint32_t b0, uint32_t b1) {
    asm volatile(
        "mma.sync.aligned.m16n8k16.row.col.f32.f16.f16.f32 "
        "{%0,%1,%2,%3}, {%4,%5,%6,%7}, {%8,%9}, {%0,%1,%2,%3};\n"
        : "+f"(c[0]), "+f"(c[1]), "+f"(c[2]), "+f"(c[3])
        : "r"(a[0]), "r"(a[1]), "r"(a[2]), "r"(a[3]), "r"(b0), "r"(b1));
}
__device__ __forceinline__ uint32_t pack_h2(float a, float b) {
    __half2 h = __floats2half2_rn(a, b);
    return *(uint32_t*)&h;
}

// ---------------------------------------------------------------------------
// fp16 GEMM, BM=64 x BN=128 x BK=32, 128 threads (4 warps of 32x64),
// 3-stage cp.async. 41.5KB smem. MINB controls occupancy target.
// C[M,N] = A[M,K] @ B[K,N], fp32 accumulate. K%32==0, M%64==0, nk>=2.
// ---------------------------------------------------------------------------
#define AS_STRIDE 40
#define BS_STRIDE 136
#define M64_AS_HALVES (64 * AS_STRIDE)       // 2560
#define M64_BS_HALVES (32 * BS_STRIDE)       // 4352
#define M64_SMEM_BYTES (3 * (M64_AS_HALVES + M64_BS_HALVES) * 2)   // 41472

template <bool HALF_OUT, int MINB>
__global__ __launch_bounds__(128, MINB)
void gemm_m64(const __half* __restrict__ A, const __half* __restrict__ B,
              void* __restrict__ Cv, float cscale, int N, int K,
              int lda, int ldb, int ldc)
{
    extern __shared__ __half smg[];
    __half* Asb = smg;
    __half* Bsb = smg + 3 * M64_AS_HALVES;

    const int tid  = threadIdx.x;
    const int warp = tid >> 5, lane = tid & 31;
    const int g    = lane >> 2, t4 = lane & 3;
    const int wm   = warp & 1, wn = warp >> 1;
    const int m0   = blockIdx.y * 64;
    const int n0   = blockIdx.x * 128;

    const int l16  = lane & 15;
    const int lhi8 = (lane >> 4) << 3;

    float acc[2][8][4];
    #pragma unroll
    for (int mt = 0; mt < 2; mt++)
        #pragma unroll
        for (int nt = 0; nt < 8; nt++)
            #pragma unroll
            for (int r = 0; r < 4; r++) acc[mt][nt][r] = 0.f;

    const int nk = K >> 5;

    auto load_stage = [&](int t, int buf) {
        __half* As = Asb + buf * M64_AS_HALVES;
        __half* Bs = Bsb + buf * M64_BS_HALVES;
        int k0 = t << 5;
        // A: 64 rows x 4 chunks (8 halves each) = 256 chunks, 2/thread
        #pragma unroll
        for (int j = 0; j < 2; j++) {
            int idx = tid + (j << 7);
            int row = idx >> 2, seg = (idx & 3) << 3;
            cp_async16(&As[row * AS_STRIDE + seg],
                       A + (size_t)(m0 + row) * lda + k0 + seg, true);
        }
        // B: 32 rows x 16 chunks = 512 chunks, 4/thread
        #pragma unroll
        for (int j = 0; j < 4; j++) {
            int idx = tid + (j << 7);
            int row = idx >> 4, seg = (idx & 15) << 3;
            int col = n0 + seg;
            bool p = col < N;
            const __half* src = p ? (B + (size_t)(k0 + row) * ldb + col) : B;
            cp_async16(&Bs[row * BS_STRIDE + seg], src, p);
        }
        cp_commit();
    };

    load_stage(0, 0);
    load_stage(1, 1);

    int buf = 0, lbuf = 2;
    for (int t = 0; t < nk; t++) {
        cp_wait<1>();
        __syncthreads();
        if (t + 2 < nk) load_stage(t + 2, lbuf);
        else            cp_commit();

        uint32_t a_base = (uint32_t)__cvta_generic_to_shared(Asb + buf * M64_AS_HALVES);
        uint32_t b_base = (uint32_t)__cvta_generic_to_shared(Bsb + buf * M64_BS_HALVES);

        #pragma unroll
        for (int ks = 0; ks < 2; ks++) {
            int k16 = ks << 4;
            uint32_t af[2][4];
            #pragma unroll
            for (int mt = 0; mt < 2; mt++) {
                uint32_t addr = a_base +
                    ((wm * 32 + mt * 16 + l16) * AS_STRIDE + k16 + lhi8) * 2u;
                ldmatrix_x4(af[mt][0], af[mt][1], af[mt][2], af[mt][3], addr);
            }
            uint32_t bf[4][4];
            #pragma unroll
            for (int ntp = 0; ntp < 4; ntp++) {
                uint32_t addr = b_base +
                    ((k16 + l16) * BS_STRIDE + wn * 64 + ntp * 16 + lhi8) * 2u;
                ldmatrix_x4_trans(bf[ntp][0], bf[ntp][1], bf[ntp][2], bf[ntp][3], addr);
            }
            #pragma unroll
            for (int mt = 0; mt < 2; mt++)
                #pragma unroll
                for (int nt = 0; nt < 8; nt++)
                    mma16816(acc[mt][nt], af[mt],
                             bf[nt >> 1][(nt & 1) * 2 + 0], bf[nt >> 1][(nt & 1) * 2 + 1]);
        }
        buf  = (buf  == 2) ? 0 : buf  + 1;
        lbuf = (lbuf == 2) ? 0 : lbuf + 1;
    }

    #pragma unroll
    for (int mt = 0; mt < 2; mt++) {
        int row = m0 + wm * 32 + mt * 16 + g;
        #pragma unroll
        for (int nt = 0; nt < 8; nt++) {
            int col = n0 + wn * 64 + nt * 8 + t4 * 2;
            if (col < N) {
                float* c = acc[mt][nt];
                if (HALF_OUT) {
                    __half* C = (__half*)Cv;
                    *(__half2*)(C + (size_t)row * ldc + col) =
                        __floats2half2_rn(c[0] * cscale, c[1] * cscale);
                    *(__half2*)(C + (size_t)(row + 8) * ldc + col) =
                        __floats2half2_rn(c[2] * cscale, c[3] * cscale);
                } else {
                    float* C = (float*)Cv;
                    *(float2*)(C + (size_t)row * ldc + col)       = make_float2(c[0], c[1]);
                    *(float2*)(C + (size_t)(row + 8) * ldc + col) = make_float2(c[2], c[3]);
                }
            }
        }
    }
}

// ---------------------------------------------------------------------------
// RMSNorm fp32 -> fp16
// ---------------------------------------------------------------------------
__global__ void rmsnorm_f16(const float* __restrict__ x, const float* __restrict__ w,
                            __half* __restrict__ out, int cols, int in_stride, int out_stride)
{
    const float* p = x + (size_t)blockIdx.x * in_stride;
    __half* q = out + (size_t)blockIdx.x * out_stride;
    float s = 0.f;
    for (int c = threadIdx.x; c < cols; c += blockDim.x) { float v = p[c]; s += v * v; }
    __shared__ float red[256];
    red[threadIdx.x] = s;
    __syncthreads();
    for (int o = 128; o > 0; o >>= 1) {
        if (threadIdx.x < o) red[threadIdx.x] += red[threadIdx.x + o];
        __syncthreads();
    }
    float scale = rsqrtf(red[0] / (float)cols + 1e-6f);
    for (int c = threadIdx.x; c < cols; c += blockDim.x)
        q[c] = __float2half_rn(p[c] * scale * w[c]);
}

// ---------------------------------------------------------------------------
// RoPE
// ---------------------------------------------------------------------------
__global__ void rope_kpe16_kernel(const float* __restrict__ qkva, __half* __restrict__ kpe)
{
    int idx = blockIdx.x * blockDim.x + threadIdx.x;
    if (idx >= SEQ * 32) return;
    int row = idx >> 5, j = idx & 31;
    float c = g_cosT[idx], s = g_sinT[idx];
    const float* p = qkva + (size_t)row * 2112 + 2048;
    float a = p[j], b = p[j + 32];
    kpe[row * 64 + j]      = __float2half_rn(a * c - b * s);
    kpe[row * 64 + j + 32] = __float2half_rn(b * c + a * s);
}

__global__ void rope_q16_kernel(__half* __restrict__ q)
{
    int idx = blockIdx.x * blockDim.x + threadIdx.x;
    if (idx >= SEQ * NH * 32) return;
    int row = idx >> 12;
    int rem = idx & 4095;
    int h   = rem >> 5, j = rem & 31;
    float c = g_cosT[row * 32 + j], s = g_sinT[row * 32 + j];
    __half* p = q + (size_t)row * (NH * DQ) + h * DQ + DNOPE;
    float a = __half2float(p[j]), b = __half2float(p[j + 32]);
    p[j]      = __float2half_rn(a * c - b * s);
    p[j + 32] = __float2half_rn(b * c + a * s);
}

// ---------------------------------------------------------------------------
// Tensor-core flash attention: 128-row q-tile, 4 warps, 32 q-rows/warp.
// Heavy-first CTA order; exp2 softmax (q pre-scaled by 192^-0.5 * log2e).
// grid = (8 mblk, 128 heads), 128 threads.
// ---------------------------------------------------------------------------
#define AQ_STR 200
#define AK_STR 200
#define AV_STR 136
#define AT_QS  0
#define AT_KS  (128 * AQ_STR)                  // 25600
#define AT_VS  (AT_KS + 64 * AK_STR)           // 38400
#define AT_SMEM_HALVES (AT_VS + 64 * AV_STR)   // 47104 halves = 94208 B

__global__ __launch_bounds__(128)
void attn_mma(const __half* __restrict__ Q, const __half* __restrict__ KV,
              const __half* __restrict__ KPE, __half* __restrict__ O)
{
    extern __shared__ __half sh[];
    __half* Qs = sh + AT_QS;
    __half* Ks = sh + AT_KS;
    __half* Vs = sh + AT_VS;

    const int h    = blockIdx.y;
    const int mblk = gridDim.x - 1 - blockIdx.x;   // heavy CTAs scheduled first
    const int m0   = mblk * 128;
    const int tid  = threadIdx.x;
    const int warp = tid >> 5, lane = tid & 31;
    const int g    = lane >> 2, t4 = lane & 3;
    const int l16  = lane & 15;
    const int lhi8 = (lane >> 4) << 3;

    for (int c = tid; c < 128 * 24; c += 128) {
        int qr = c / 24, sg = c % 24;
        cp_async16(&Qs[qr * AQ_STR + sg * 8],
                   Q + (size_t)(m0 + qr) * (NH * DQ) + h * DQ + sg * 8, true);
    }
    cp_commit();

    float accO[2][16][4];
    #pragma unroll
    for (int mt = 0; mt < 2; mt++)
        #pragma unroll
        for (int i = 0; i < 16; i++)
            #pragma unroll
            for (int r = 0; r < 4; r++) accO[mt][i][r] = 0.f;
    float m_run[2][2] = {{-1e30f, -1e30f}, {-1e30f, -1e30f}};
    float l_run[2][2] = {{0.f, 0.f}, {0.f, 0.f}};

    uint32_t qbase = (uint32_t)__cvta_generic_to_shared(Qs);
    uint32_t kbase = (uint32_t)__cvta_generic_to_shared(Ks);
    uint32_t vbase = (uint32_t)__cvta_generic_to_shared(Vs);

    const int ntiles = 2 * mblk + 2;
    for (int nt = 0; nt < ntiles; nt++) {
        int n0 = nt * 64;
        for (int c = tid; c < 64 * 24; c += 128) {
            int kr = c / 24, sg = c % 24;
            if (sg < 16)
                cp_async16(&Ks[kr * AK_STR + sg * 8],
                           KV + (size_t)(n0 + kr) * (NH * 256) + h * 256 + sg * 8, true);
            else
                cp_async16(&Ks[kr * AK_STR + 128 + (sg - 16) * 8],
                           KPE + (size_t)(n0 + kr) * 64 + (sg - 16) * 8, true);
        }
        for (int c = tid; c < 64 * 16; c += 128) {
            int vr = c / 16, sg = c % 16;
            cp_async16(&Vs[vr * AV_STR + sg * 8],
                       KV + (size_t)(n0 + vr) * (NH * 256) + h * 256 + 128 + sg * 8, true);
        }
        cp_commit();
        cp_wait<0>();
        __syncthreads();

        float sacc[2][8][4];
        #pragma unroll
        for (int mt = 0; mt < 2; mt++)
            #pragma unroll
            for (int nb = 0; nb < 8; nb++)
                #pragma unroll
                for (int r = 0; r < 4; r++) sacc[mt][nb][r] = 0.f;

        #pragma unroll
        for (int kk = 0; kk < 12; kk++) {
            uint32_t aq[2][4];
            #pragma unroll
            for (int mt = 0; mt < 2; mt++)
                ldmatrix_x4(aq[mt][0], aq[mt][1], aq[mt][2], aq[mt][3],
                            qbase + ((warp * 32 + mt * 16 + l16) * AQ_STR + kk * 16 + lhi8) * 2u);
            #pragma unroll
            for (int nb2 = 0; nb2 < 4; nb2++) {
                uint32_t bk[4];
                ldmatrix_x4(bk[0], bk[1], bk[2], bk[3],
                            kbase + ((nb2 * 16 + l16) * AK_STR + kk * 16 + lhi8) * 2u);
                #pragma unroll
                for (int mt = 0; mt < 2; mt++) {
                    mma16816(sacc[mt][nb2 * 2],     aq[mt], bk[0], bk[2]);
                    mma16816(sacc[mt][nb2 * 2 + 1], aq[mt], bk[1], bk[3]);
                }
            }
        }

        if (nt >= 2 * mblk) {
            #pragma unroll
            for (int mt = 0; mt < 2; mt++) {
                int row0 = m0 + warp * 32 + mt * 16 + g;
                #pragma unroll
                for (int nb = 0; nb < 8; nb++) {
                    int c0 = n0 + nb * 8 + 2 * t4;
                    if (c0     > row0)     sacc[mt][nb][0] = -1e30f;
                    if (c0 + 1 > row0)     sacc[mt][nb][1] = -1e30f;
                    if (c0     > row0 + 8) sacc[mt][nb][2] = -1e30f;
                    if (c0 + 1 > row0 + 8) sacc[mt][nb][3] = -1e30f;
                }
            }
        }

        #pragma unroll
        for (int mt = 0; mt < 2; mt++) {
            float mx0 = -1e30f, mx1 = -1e30f;
            #pragma unroll
            for (int nb = 0; nb < 8; nb++) {
                mx0 = fmaxf(mx0, fmaxf(sacc[mt][nb][0], sacc[mt][nb][1]));
                mx1 = fmaxf(mx1, fmaxf(sacc[mt][nb][2], sacc[mt][nb][3]));
            }
            mx0 = fmaxf(mx0, __shfl_xor_sync(0xffffffffu, mx0, 1));
            mx0 = fmaxf(mx0, __shfl_xor_sync(0xffffffffu, mx0, 2));
            mx1 = fmaxf(mx1, __shfl_xor_sync(0xffffffffu, mx1, 1));
            mx1 = fmaxf(mx1, __shfl_xor_sync(0xffffffffu, mx1, 2));

            float mn0 = fmaxf(m_run[mt][0], mx0), mn1 = fmaxf(m_run[mt][1], mx1);
            float corr0 = exp2f(m_run[mt][0] - mn0), corr1 = exp2f(m_run[mt][1] - mn1);

            float ls0 = 0.f, ls1 = 0.f;
            #pragma unroll
            for (int nb = 0; nb < 8; nb++) {
                float p0 = exp2f(sacc[mt][nb][0] - mn0);
                float p1 = exp2f(sacc[mt][nb][1] - mn0);
                float p2 = exp2f(sacc[mt][nb][2] - mn1);
                float p3 = exp2f(sacc[mt][nb][3] - mn1);
                ls0 += p0 + p1;
                ls1 += p2 + p3;
                sacc[mt][nb][0] = p0; sacc[mt][nb][1] = p1;
                sacc[mt][nb][2] = p2; sacc[mt][nb][3] = p3;
            }
            ls0 += __shfl_xor_sync(0xffffffffu, ls0, 1);
            ls0 += __shfl_xor_sync(0xffffffffu, ls0, 2);
            ls1 += __shfl_xor_sync(0xffffffffu, ls1, 1);
            ls1 += __shfl_xor_sync(0xffffffffu, ls1, 2);
            l_run[mt][0] = l_run[mt][0] * corr0 + ls0;
            l_run[mt][1] = l_run[mt][1] * corr1 + ls1;
            m_run[mt][0] = mn0; m_run[mt][1] = mn1;

            #pragma unroll
            for (int i = 0; i < 16; i++) {
                accO[mt][i][0] *= corr0; accO[mt][i][1] *= corr0;
                accO[mt][i][2] *= corr1; accO[mt][i][3] *= corr1;
            }
        }

        #pragma unroll
        for (int kb = 0; kb < 4; kb++) {
            uint32_t pa[2][4];
            #pragma unroll
            for (int mt = 0; mt < 2; mt++) {
                pa[mt][0] = pack_h2(sacc[mt][2 * kb][0],     sacc[mt][2 * kb][1]);
                pa[mt][1] = pack_h2(sacc[mt][2 * kb][2],     sacc[mt][2 * kb][3]);
                pa[mt][2] = pack_h2(sacc[mt][2 * kb + 1][0], sacc[mt][2 * kb + 1][1]);
                pa[mt][3] = pack_h2(sacc[mt][2 * kb + 1][2], sacc[mt][2 * kb + 1][3]);
            }
            #pragma unroll
            for (int np = 0; np < 8; np++) {
                uint32_t bv[4];
                ldmatrix_x4_trans(bv[0], bv[1], bv[2], bv[3],
                                  vbase + ((kb * 16 + l16) * AV_STR + np * 16 + lhi8) * 2u);
                #pragma unroll
                for (int mt = 0; mt < 2; mt++) {
                    mma16816(accO[mt][np * 2],     pa[mt], bv[0], bv[1]);
                    mma16816(accO[mt][np * 2 + 1], pa[mt], bv[2], bv[3]);
                }
            }
        }
        __syncthreads();
    }

    #pragma unroll
    for (int mt = 0; mt < 2; mt++) {
        float inv0 = 1.f / l_run[mt][0], inv1 = 1.f / l_run[mt][1];
        int row0 = m0 + warp * 32 + mt * 16 + g;
        __half* O0 = O + (size_t)row0 * (NH * DVDIM) + h * DVDIM;
        __half* O1 = O0 + 8 * (size_t)(NH * DVDIM);
        #pragma unroll
        for (int np = 0; np < 16; np++) {
            int col = np * 8 + 2 * t4;
            *(__half2*)(O0 + col) =
                __floats2half2_rn(accO[mt][np][0] * inv0, accO[mt][np][1] * inv0);
            *(__half2*)(O1 + col) =
                __floats2half2_rn(accO[mt][np][2] * inv1, accO[mt][np][3] * inv1);
        }
    }
}

// ---------------------------------------------------------------------------
extern "C" void kernel_launch(void* const* d_in, const int* in_sizes, int n_in,
                              void* d_out, int out_size)
{
    const float* x    = (const float*)d_in[0];
    // d_in[1] = position_ids = arange(S); row index used directly (dtype-proof).
    const float* wqa  = (const float*)d_in[2];
    const float* qln  = (const float*)d_in[3];
    const float* wqb  = (const float*)d_in[4];
    const float* wkva = (const float*)d_in[5];
    const float* kvln = (const float*)d_in[6];
    const float* wkvb = (const float*)d_in[7];
    const float* wo   = (const float*)d_in[8];
    float*       out  = (float*)d_out;

    float *qkva;
    __half *x16, *qa16, *kva16, *q16, *kv16, *kpe16, *ao16;
    __half *wab16, *wqb16, *wkvb16, *wo16;
    cudaGetSymbolAddress((void**)&qkva,   g_qkva);
    cudaGetSymbolAddress((void**)&x16,    g_x16);
    cudaGetSymbolAddress((void**)&qa16,   g_qa16);
    cudaGetSymbolAddress((void**)&kva16,  g_kva16);
    cudaGetSymbolAddress((void**)&q16,    g_q16);
    cudaGetSymbolAddress((void**)&kv16,   g_kv16);
    cudaGetSymbolAddress((void**)&kpe16,  g_kpe16);
    cudaGetSymbolAddress((void**)&ao16,   g_ao16);
    cudaGetSymbolAddress((void**)&wab16,  g_wab16);
    cudaGetSymbolAddress((void**)&wqb16,  g_wqb16);
    cudaGetSymbolAddress((void**)&wkvb16, g_wkvb16);
    cudaGetSymbolAddress((void**)&wo16,   g_wo16);

    static cudaStream_t s1 = nullptr;
    static cudaEvent_t ev_root = nullptr, ev_q = nullptr, ev_k = nullptr, ev_o = nullptr;
    if (s1 == nullptr) {
        cudaStreamCreateWithFlags(&s1, cudaStreamNonBlocking);
        cudaEventCreateWithFlags(&ev_root, cudaEventDisableTiming);
        cudaEventCreateWithFlags(&ev_q,    cudaEventDisableTiming);
        cudaEventCreateWithFlags(&ev_k,    cudaEventDisableTiming);
        cudaEventCreateWithFlags(&ev_o,    cudaEventDisableTiming);
    }

    auto cvt_on = [&](cudaStream_t st, const float* src, __half* dst, long long n) {
        long long n16 = n / 16;
        int blocks = (int)((n16 + 255) / 256);
        if (blocks > 16384) blocks = 16384;
        cvt_f16_copy<<<blocks, 256, 0, st>>>(src, dst, n16);
    };

    // fork: side stream converts the three big weights
    cudaEventRecord(ev_root, 0);
    cudaStreamWaitEvent(s1, ev_root, 0);
    cvt_on(s1, wqb,  wqb16,  (long long)1536 * 24576);
    cudaEventRecord(ev_q, s1);
    cvt_on(s1, wkvb, wkvb16, (long long)512 * 32768);
    cudaEventRecord(ev_k, s1);
    cvt_on(s1, wo,   wo16,   (long long)16384 * HID);
    cudaEventRecord(ev_o, s1);

    // main stream
    cvt_on(0, x, x16, (long long)SEQ * HID);
    cvt_f16_strided<<<2048, 256>>>(wqa,  wab16, HID, 1536 / 8, 2112, 0);
    cvt_f16_strided<<<1024, 256>>>(wkva, wab16, HID, 576 / 8,  2112, 1536);
    rope_table_kernel<<<(SEQ * 32 + 255) / 256, 256>>>();

    // 192^-0.5 * log2(e): softmax computed base-2 (exp2f).
    const float qscale = 0.07216878364870323f * 1.4426950408889634f;

    cudaFuncSetAttribute((const void*)gemm_m64<false, 4>,
                         cudaFuncAttributeMaxDynamicSharedMemorySize, M64_SMEM_BYTES);
    cudaFuncSetAttribute((const void*)gemm_m64<true, 4>,
                         cudaFuncAttributeMaxDynamicSharedMemorySize, M64_SMEM_BYTES);
    cudaFuncSetAttribute((const void*)gemm_m64<true, 3>,
                         cudaFuncAttributeMaxDynamicSharedMemorySize, M64_SMEM_BYTES);

    // 1: merged q_a|kv_a projection -> fp32 [1024, 2112]  (272 CTAs)
    gemm_m64<false, 4><<<dim3(17, 16), 128, M64_SMEM_BYTES>>>(
        x16, wab16, qkva, 1.f, 2112, HID, HID, 2112, 2112);

    // 2: rmsnorms -> fp16
    rmsnorm_f16<<<SEQ, 256>>>(qkva,        qln,  qa16,  1536, 2112, 1536);
    rmsnorm_f16<<<SEQ, 256>>>(qkva + 1536, kvln, kva16, 512,  2112, 512);

    // 3: rope on k_pe
    rope_kpe16_kernel<<<(SEQ * 32 + 255) / 256, 256>>>(qkva, kpe16);

    // 4: q projection (needs wqb16) + rope on q_pe  (3072 CTAs, occ3)
    cudaStreamWaitEvent(0, ev_q, 0);
    gemm_m64<true, 3><<<dim3(24576 / 128, 16), 128, M64_SMEM_BYTES>>>(
        qa16, wqb16, q16, qscale, 24576, 1536, 1536, 24576, 24576);
    rope_q16_kernel<<<(SEQ * NH * 32 + 255) / 256, 256>>>(q16);

    // 5: kv projection (needs wkvb16)  (4096 CTAs, occ4)
    cudaStreamWaitEvent(0, ev_k, 0);
    gemm_m64<true, 4><<<dim3(32768 / 128, 16), 128, M64_SMEM_BYTES>>>(
        kva16, wkvb16, kv16, 1.f, 32768, 512, 512, 32768, 32768);

    // 6: attention (128-row q-tiles, heavy-first order)
    cudaFuncSetAttribute(attn_mma, cudaFuncAttributeMaxDynamicSharedMemorySize,
                         AT_SMEM_HALVES * 2);
    attn_mma<<<dim3(8, NH), 128, AT_SMEM_HALVES * 2>>>(q16, kv16, kpe16, ao16);

    // 7: output projection (needs wo16) -> d_out  (896 CTAs, occ4: 2 clean waves)
    cudaStreamWaitEvent(0, ev_o, 0);
    gemm_m64<false, 4><<<dim3(HID / 128, 16), 128, M64_SMEM_BYTES>>>(
        ao16, wo16, out, 1.f, HID, NH * DVDIM, NH * DVDIM, HID, HID);
}